// round 8
// baseline (speedup 1.0000x reference)
#include <cuda_runtime.h>

#define Ww 112
#define NP (112*112)
#define NCH 64
#define RS 29                 // shared row stride in float4 units (odd mod 8)
#define NR 60                 // rows held per CTA (half plane + halo)
#define G4 28                 // float4 groups per image row

__device__ __forceinline__ float rcpa(float x) {
    float y; asm("rcp.approx.f32 %0, %1;" : "=f"(y) : "f"(x)); return y;
}

// 4 outputs with ONE MUFU.RCP: r = 1/(d0 d1 d2 d3), recover each 1/di.
__device__ __forceinline__ float4 norm4v(float4 n, float d0, float d1,
                                         float d2, float d3,
                                         float wgt, float bs) {
    const float d01 = d0*d1, d23 = d2*d3;
    const float r   = rcpa(d01*d23);
    const float r01 = r*d23, r23 = r*d01;
    float4 o;
    o.x = fmaf(wgt*n.x, r01*d1, bs);
    o.y = fmaf(wgt*n.y, r01*d0, bs);
    o.z = fmaf(wgt*n.z, r23*d3, bs);
    o.w = fmaf(wgt*n.w, r23*d2, bs);
    return o;
}

__global__ __launch_bounds__(256, 5)
void bionorm_kernel(const float* __restrict__ x,
                    const float* __restrict__ sigma,
                    const float* __restrict__ pow_p,
                    const float* __restrict__ ker,
                    const float* __restrict__ weight,
                    const float* __restrict__ bias,
                    float* __restrict__ out)
{
    __shared__ float4 s4[NR * RS];          // 27840 B: xp, then H in place

    const int bid   = blockIdx.x;
    const int plane = bid >> 1;             // b*C + c
    const int half  = bid & 1;
    const int c     = plane & (NCH - 1);
    const int r0    = half ? 52 : 0;        // first loaded plane row
    const int yb    = half ? 56 : 0;        // first output row
    const int tid   = threadIdx.x;

    const float* __restrict__ xin = x + (size_t)plane * NP;
    const float4* __restrict__ xg4 = reinterpret_cast<const float4*>(xin);
    float4* __restrict__ po4 =
        reinterpret_cast<float4*>(out + (size_t)plane * NP);

    const float p  = pow_p[c];
    const bool  p2 = (p == 2.0f);

    // ---- Phase 1a: float4 load + x^p -> shared (rows r0..r0+59) ----
    const float4* __restrict__ xin4 = xg4 + r0 * G4;
    for (int i = tid; i < NR * G4; i += 256) {
        const int ly = i / G4;
        const int g  = i - ly * G4;
        float4 v = xin4[i];
        float4 rq;
        if (p2) {
            rq.x = v.x*v.x; rq.y = v.y*v.y; rq.z = v.z*v.z; rq.w = v.w*v.w;
        } else {
            rq.x = __powf(v.x, p); rq.y = __powf(v.y, p);
            rq.z = __powf(v.z, p); rq.w = __powf(v.w, p);
        }
        s4[ly * RS + g] = rq;
    }

    // ---- per-channel params: rank-1 + unit-row detection (block-uniform) ----
    const float* __restrict__ kerg = ker + c * 25;
    float maxa = 0.0f, best = -1.0f; int pi = 0;
#pragma unroll
    for (int i = 0; i < 25; i++) {
        const float a = fabsf(__ldg(kerg + i));
        maxa = fmaxf(maxa, a);
        if (a > best) { best = a; pi = i; }
    }
    const int i0 = pi / 5, j0 = pi - i0 * 5;

    float rk[5], ck[5];
    int mode = 2;                           // 0: rows all equal (slide)
    if (maxa > 0.0f) {                      // 1: separable  2: general
        const float inv = 1.0f / __ldg(kerg + pi);
#pragma unroll
        for (int i = 0; i < 5; i++) rk[i] = __ldg(kerg + i*5 + j0) * inv;
#pragma unroll
        for (int j = 0; j < 5; j++) ck[j] = __ldg(kerg + i0*5 + j);
        bool sep = true;
        const float tol = 1e-6f * maxa;
#pragma unroll
        for (int i = 0; i < 5; i++)
#pragma unroll
            for (int j = 0; j < 5; j++)
                if (fabsf(fmaf(-rk[i], ck[j], __ldg(kerg + i*5 + j))) > tol)
                    sep = false;
        if (sep) {
            bool unit = true;
#pragma unroll
            for (int i = 0; i < 5; i++)
                if (fabsf(rk[i] - 1.0f) > 1e-6f) unit = false;
            mode = unit ? 0 : 1;
        }
    } else {
#pragma unroll
        for (int i = 0; i < 5; i++) { rk[i] = 1.0f; ck[i] = 0.0f; }
        mode = 0;                           // zero kernel
    }
    const float c0 = ck[0], c1 = ck[1], c2 = ck[2], c3 = ck[3], c4 = ck[4];

    const float sgm = sigma[c];
    const float sp  = p2 ? sgm*sgm : __powf(sgm, p);
    const float wgt = weight[c];
    const float bs  = bias[c];

    __syncthreads();

    // ---- Phase 1b (modes 0,1): in-place ck horizontal pass, x-edges baked ----
    // thread t owns row t; in-place safe: window values live in regs A,B,C.
    if (mode < 2 && tid < NR) {
        float4* rp = s4 + tid * RS;
        float4 A, B = rp[0], C = rp[1];
        {   // group 0: x=0..3, centers 2,2,2,3
            float h2 = c0*B.x + c1*B.y + c2*B.z + c3*B.w + c4*C.x;
            float h3 = c0*B.y + c1*B.z + c2*B.w + c3*C.x + c4*C.y;
            rp[0] = make_float4(h2, h2, h2, h3);
        }
        A = B; B = C;
#pragma unroll 2
        for (int gw = 1; gw < 27; gw++) {
            C = rp[gw + 1];
            float h0 = c0*A.z + c1*A.w + c2*B.x + c3*B.y + c4*B.z;
            float h1 = c0*A.w + c1*B.x + c2*B.y + c3*B.z + c4*B.w;
            float h2 = c0*B.x + c1*B.y + c2*B.z + c3*B.w + c4*C.x;
            float h3 = c0*B.y + c1*B.z + c2*B.w + c3*C.x + c4*C.y;
            rp[gw] = make_float4(h0, h1, h2, h3);
            A = B; B = C;
        }
        {   // group 27: x=108..111, centers 108,109,109,109
            float h0 = c0*A.z + c1*A.w + c2*B.x + c3*B.y + c4*B.z;
            float h1 = c0*A.w + c1*B.x + c2*B.y + c3*B.z + c4*B.w;
            rp[27] = make_float4(h0, h1, h1, h1);
        }
    }
    __syncthreads();

    // ---- Phase 2: 28 x-groups (4-wide) x 8 strips of 7 rows = 224 threads ----
    if (tid < 224) {
        const int xg    = tid >> 3;         // 0..27, float4 group == xg
        const int strip = tid & 7;          // 0..7
        const int y0    = yb + strip * 7;

        int cy = min(max(y0, 2), 109);
        float t0, t1, t2, t3;
        float den0, den1, den2, den3;

        if (mode == 0) {
            // init vertical sum over H rows cy-2..cy+2
            float4 q = s4[(cy - 2 - r0) * RS + xg];
            t0 = q.x; t1 = q.y; t2 = q.z; t3 = q.w;
#pragma unroll
            for (int rr = 1; rr < 5; rr++) {
                q = s4[(cy - 2 + rr - r0) * RS + xg];
                t0 += q.x; t1 += q.y; t2 += q.z; t3 += q.w;
            }
        }

#pragma unroll 1
        for (int y = y0; y < y0 + 7; y++) {
            const int cyn = min(max(y, 2), 109);
            if (mode == 0) {
                if (cyn != cy) {
                    const float4 e = s4[(cyn + 2 - r0) * RS + xg];
                    const float4 l = s4[(cyn - 3 - r0) * RS + xg];
                    t0 += e.x - l.x; t1 += e.y - l.y;
                    t2 += e.z - l.z; t3 += e.w - l.w;
                    cy = cyn;
                }
                den0 = sp + t0; den1 = sp + t1;
                den2 = sp + t2; den3 = sp + t3;
            } else if (mode == 1) {
                // vertical rk-weighted rebuild from H
                float a0 = 0, a1 = 0, a2 = 0, a3 = 0;
#pragma unroll
                for (int rr = 0; rr < 5; rr++) {
                    const float4 q = s4[(cyn - 2 + rr - r0) * RS + xg];
                    const float w = rk[rr];
                    a0 = fmaf(w, q.x, a0); a1 = fmaf(w, q.y, a1);
                    a2 = fmaf(w, q.z, a2); a3 = fmaf(w, q.w, a3);
                }
                den0 = sp + a0; den1 = sp + a1;
                den2 = sp + a2; den3 = sp + a3;
            } else {
                // general scalar 25-tap on xp (cold path, correctness only)
                const float* sf = reinterpret_cast<const float*>(s4);
                float d[4];
#pragma unroll
                for (int j = 0; j < 4; j++) {
                    const int cx = min(max(4*xg + j, 2), 109);
                    float a = 0.0f;
                    for (int rr = 0; rr < 5; rr++)
                        for (int tt = 0; tt < 5; tt++)
                            a = fmaf(__ldg(kerg + rr*5 + tt),
                                     sf[(cyn - 2 + rr - r0) * (RS*4)
                                        + (cx - 2 + tt)], a);
                    d[j] = sp + a;
                }
                den0 = d[0]; den1 = d[1]; den2 = d[2]; den3 = d[3];
            }

            // numerator xp from global (L2-resident) + normalize + store
            float4 v = xg4[y * G4 + xg];
            float4 n;
            if (p2) {
                n.x = v.x*v.x; n.y = v.y*v.y; n.z = v.z*v.z; n.w = v.w*v.w;
            } else {
                n.x = __powf(v.x, p); n.y = __powf(v.y, p);
                n.z = __powf(v.z, p); n.w = __powf(v.w, p);
            }
            po4[y * G4 + xg] = norm4v(n, den0, den1, den2, den3, wgt, bs);
        }
    }
}

extern "C" void kernel_launch(void* const* d_in, const int* in_sizes, int n_in,
                              void* d_out, int out_size)
{
    const float* x      = (const float*)d_in[0];
    const float* sigma  = (const float*)d_in[1];
    const float* pow_p  = (const float*)d_in[2];
    const float* ker    = (const float*)d_in[3];
    const float* weight = (const float*)d_in[4];
    const float* bias   = (const float*)d_in[5];
    float* out = (float*)d_out;

    bionorm_kernel<<<32 * NCH * 2, 256>>>(x, sigma, pow_p, ker,
                                          weight, bias, out);
}

// round 10
// speedup vs baseline: 1.3412x; 1.3412x over previous
#include <cuda_runtime.h>

#define Ww 112
#define NP (112*112)
#define NCH 64
#define G4 28                 // float4 groups per row

__device__ __forceinline__ float rcpa(float x) {
    float y; asm("rcp.approx.f32 %0, %1;" : "=f"(y) : "f"(x)); return y;
}

__device__ __forceinline__ float4 pw4(float4 v, float p, bool p2) {
    float4 r;
    if (p2) { r.x=v.x*v.x; r.y=v.y*v.y; r.z=v.z*v.z; r.w=v.w*v.w; }
    else    { r.x=__powf(v.x,p); r.y=__powf(v.y,p);
              r.z=__powf(v.z,p); r.w=__powf(v.w,p); }
    return r;
}

// 4 outputs with ONE MUFU.RCP
__device__ __forceinline__ float4 norm4v(float4 n, float d0, float d1,
                                         float d2, float d3,
                                         float wgt, float bs) {
    const float d01 = d0*d1, d23 = d2*d3;
    const float r   = rcpa(d01*d23);
    const float r01 = r*d23, r23 = r*d01;
    float4 o;
    o.x = fmaf(wgt*n.x, r01*d1, bs);
    o.y = fmaf(wgt*n.y, r01*d0, bs);
    o.z = fmaf(wgt*n.z, r23*d3, bs);
    o.w = fmaf(wgt*n.w, r23*d2, bs);
    return o;
}

__global__ __launch_bounds__(256, 5)
void bionorm_kernel(const float* __restrict__ x,
                    const float* __restrict__ sigma,
                    const float* __restrict__ pow_p,
                    const float* __restrict__ ker,
                    const float* __restrict__ weight,
                    const float* __restrict__ bias,
                    float* __restrict__ out)
{
    const int plane = blockIdx.x;           // b*C + c
    const int c     = plane & (NCH - 1);
    const int warp  = threadIdx.x >> 5;
    const int lane  = threadIdx.x & 31;
    const int xl    = min(lane, 27);        // owned float4 group (lanes 28-31 shadow 27)
    const bool act  = lane < 28;

    const float4* __restrict__ xp4 =
        reinterpret_cast<const float4*>(x + (size_t)plane * NP);
    float4* __restrict__ po4 =
        reinterpret_cast<float4*>(out + (size_t)plane * NP);

    const float p  = pow_p[c];
    const bool  p2 = (p == 2.0f);

    // ---- per-channel params: rank-1 / unit-rk / uniform-ck detection ----
    const float* __restrict__ kerg = ker + c * 25;
    float maxa = 0.0f, best = -1.0f; int pi = 0;
#pragma unroll
    for (int i = 0; i < 25; i++) {
        const float a = fabsf(__ldg(kerg + i));
        maxa = fmaxf(maxa, a);
        if (a > best) { best = a; pi = i; }
    }
    const int i0 = pi / 5, j0 = pi - i0 * 5;

    float rk[5], ck[5];
    int mode = 2;          // 0: unit row weights (slide)  1: separable  2: general
    bool uni = false;      // ck all equal (sliding h)
    if (maxa > 0.0f) {
        const float inv = 1.0f / __ldg(kerg + pi);
#pragma unroll
        for (int i = 0; i < 5; i++) rk[i] = __ldg(kerg + i*5 + j0) * inv;
#pragma unroll
        for (int j = 0; j < 5; j++) ck[j] = __ldg(kerg + i0*5 + j);
        bool sep = true;
        const float tol = 1e-6f * maxa;
#pragma unroll
        for (int i = 0; i < 5; i++)
#pragma unroll
            for (int j = 0; j < 5; j++)
                if (fabsf(fmaf(-rk[i], ck[j], __ldg(kerg + i*5 + j))) > tol)
                    sep = false;
        if (sep) {
            bool unit = true;
#pragma unroll
            for (int i = 0; i < 5; i++)
                if (fabsf(rk[i] - 1.0f) > 1e-6f) unit = false;
            mode = unit ? 0 : 1;
            uni = true;
            const float utol = 1e-6f * fabsf(ck[0]);
#pragma unroll
            for (int j = 1; j < 5; j++)
                if (fabsf(ck[j] - ck[0]) > utol) uni = false;
        }
    } else {
#pragma unroll
        for (int i = 0; i < 5; i++) { rk[i] = 1.0f; ck[i] = 0.0f; }
        mode = 0; uni = true;
    }
    const float w25 = ck[0];
    const float k0 = ck[0], k1 = ck[1], k2 = ck[2], k3 = ck[3], k4 = ck[4];

    const float sgm = sigma[c];
    const float sp  = p2 ? sgm*sgm : __powf(sgm, p);
    const float wgt = weight[c];
    const float bs  = bias[c];

    const int y0 = warp * 14;                 // this warp's 14-row strip
    int cy = min(max(y0, 2), 109);

    float t0 = 0, t1 = 0, t2 = 0, t3 = 0;     // vertical column sums
    if (mode == 0) {
#pragma unroll
        for (int rr = 0; rr < 5; rr++) {
            float4 q = pw4(xp4[(cy - 2 + rr) * G4 + xl], p, p2);
            t0 += q.x; t1 += q.y; t2 += q.z; t3 += q.w;
        }
    }

#pragma unroll 2
    for (int y = y0; y < y0 + 14; y++) {
        const int cyn = min(max(y, 2), 109);
        float d0, d1, d2, d3;

        if (mode < 2) {
            if (mode == 0) {
                if (cyn != cy) {               // warp-uniform branch
                    float4 e = pw4(xp4[(cyn + 2) * G4 + xl], p, p2);
                    float4 l = pw4(xp4[(cyn - 3) * G4 + xl], p, p2);
                    t0 += e.x - l.x; t1 += e.y - l.y;
                    t2 += e.z - l.z; t3 += e.w - l.w;
                    cy = cyn;
                }
            } else {                            // mode 1: rk-weighted rebuild
                t0 = t1 = t2 = t3 = 0.0f;
#pragma unroll
                for (int rr = 0; rr < 5; rr++) {
                    float4 q = pw4(xp4[(cyn - 2 + rr) * G4 + xl], p, p2);
                    const float w = rk[rr];
                    t0 = fmaf(w, q.x, t0); t1 = fmaf(w, q.y, t1);
                    t2 = fmaf(w, q.z, t2); t3 = fmaf(w, q.w, t3);
                }
            }

            // halo columns from neighbor lanes
            const float am2 = __shfl_up_sync(0xFFFFFFFFu, t2, 1);
            const float am1 = __shfl_up_sync(0xFFFFFFFFu, t3, 1);
            const float a4  = __shfl_down_sync(0xFFFFFFFFu, t0, 1);
            const float a5  = __shfl_down_sync(0xFFFFFFFFu, t1, 1);

            float h0, h1, h2, h3;
            if (uni) {                          // sliding plain 5-sums
                h0 = ((am2 + am1) + (t0 + t1)) + t2;
                h1 = h0 - am2 + t3;
                h2 = h1 - am1 + a4;
                h3 = h2 - t0 + a5;
            } else {                            // ck-weighted windows
                h0 = k0*am2 + k1*am1 + k2*t0 + k3*t1 + k4*t2;
                h1 = k0*am1 + k1*t0  + k2*t1 + k3*t2 + k4*t3;
                h2 = k0*t0  + k1*t1  + k2*t2 + k3*t3 + k4*a4;
                h3 = k0*t1  + k1*t2  + k2*t3 + k3*a4 + k4*a5;
            }
            if (lane == 0)  { h0 = h2; h1 = h2; }   // x-replicate left
            if (lane == 27) { h2 = h1; h3 = h1; }   // x-replicate right

            if (uni) {
                d0 = fmaf(w25, h0, sp); d1 = fmaf(w25, h1, sp);
                d2 = fmaf(w25, h2, sp); d3 = fmaf(w25, h3, sp);
            } else {
                d0 = sp + h0; d1 = sp + h1; d2 = sp + h2; d3 = sp + h3;
            }
        } else {
            // ---- mode 2: general 25-tap gather (cold, correctness only) ----
            const float* xs = reinterpret_cast<const float*>(xp4);
            float dd[4];
#pragma unroll
            for (int j = 0; j < 4; j++) {
                const int cx = min(max(4*xl + j, 2), 109);
                float a = 0.0f;
                for (int rr = 0; rr < 5; rr++)
                    for (int tt = 0; tt < 5; tt++) {
                        float v = __ldg(xs + (cyn-2+rr)*Ww + (cx-2+tt));
                        float xv = p2 ? v*v : __powf(v, p);
                        a = fmaf(__ldg(kerg + rr*5 + tt), xv, a);
                    }
                dd[j] = sp + a;
            }
            d0 = dd[0]; d1 = dd[1]; d2 = dd[2]; d3 = dd[3];
        }

        // numerator (L1-resident reload) + normalize + store
        const float4 n = pw4(xp4[y * G4 + xl], p, p2);
        if (act)
            po4[y * G4 + xl] = norm4v(n, d0, d1, d2, d3, wgt, bs);
    }
}

extern "C" void kernel_launch(void* const* d_in, const int* in_sizes, int n_in,
                              void* d_out, int out_size)
{
    const float* x      = (const float*)d_in[0];
    const float* sigma  = (const float*)d_in[1];
    const float* pow_p  = (const float*)d_in[2];
    const float* ker    = (const float*)d_in[3];
    const float* weight = (const float*)d_in[4];
    const float* bias   = (const float*)d_in[5];
    float* out = (float*)d_out;

    bionorm_kernel<<<32 * NCH, 256>>>(x, sigma, pow_p, ker,
                                      weight, bias, out);
}